// round 10
// baseline (speedup 1.0000x reference)
#include <cuda_runtime.h>
#include <math.h>

#define BATCH 16
#define HH 512
#define WW 512
#define W4 (WW / 4)      // 128 float4 per row
#define WIN 15
#define RAD 7
#define NT 256
#define NB1 512          // k1 CTAs: (4, 8, 16)
#define NB2 4096         // k2 CTAs: (4, 64, 16)
#define NBTOT (NB1 + NB2)

// Intermediate vertical box-sum maps (static scratch; 16 MB each).
__device__ float4 g_vI[(size_t)BATCH * HH * W4];
__device__ float4 g_vJ[(size_t)BATCH * HH * W4];

// Partial sums: [pII,pJJ,pIJ,sII,sJJ,sIJ] per CTA slot.
__device__ double g_part[NBTOT][6];
__device__ unsigned int g_count = 0;

// ========================= Kernel 1: vertical pass ===========================
// grid (4, 8, 16); 256 threads. lane -> float4 column, warp -> 8-row group.
// All loads/stores coalesced (consecutive lanes -> consecutive float4).
__global__ void __launch_bounds__(NT)
ncc_k1(const float* __restrict__ I, const float* __restrict__ J) {
    const int tid  = threadIdx.x;
    const int lane = tid & 31;
    const int wrp  = tid >> 5;
    const int bx = blockIdx.x, by = blockIdx.y, bz = blockIdx.z;

    const int c4 = bx * 32 + lane;            // float4 col index (0..127)
    const int y0 = (by * 8 + wrp) * 8;        // first owned row (0..504)
    const int cx = c4 * 4;

    const float4* __restrict__ I4 = (const float4*)I + (size_t)bz * HH * W4;
    const float4* __restrict__ J4 = (const float4*)J + (size_t)bz * HH * W4;
    float4* __restrict__ vI = g_vI + (size_t)bz * HH * W4;
    float4* __restrict__ vJ = g_vJ + (size_t)bz * HH * W4;

    const float wx0 = (float)(min(cx + 0 + RAD, WW - 1) - max(cx + 0 - RAD, 0) + 1);
    const float wx1 = (float)(min(cx + 1 + RAD, WW - 1) - max(cx + 1 - RAD, 0) + 1);
    const float wx2 = (float)(min(cx + 2 + RAD, WW - 1) - max(cx + 2 - RAD, 0) + 1);
    const float wx3 = (float)(min(cx + 3 + RAD, WW - 1) - max(cx + 3 - RAD, 0) + 1);

    float4 VI = make_float4(0.f, 0.f, 0.f, 0.f);
    float4 VJ = make_float4(0.f, 0.f, 0.f, 0.f);
    float pII = 0.f, pJJ = 0.f, pIJ = 0.f;

    // init window rows y0-7 .. y0+7; owned rows y0..y0+7 are k=7..14.
    #pragma unroll
    for (int k = 0; k < WIN; k++) {
        const int gy = y0 - RAD + k;
        float4 vi = make_float4(0.f, 0.f, 0.f, 0.f);
        float4 vj = vi;
        if (gy >= 0 && gy < HH) {
            vi = __ldg(I4 + gy * W4 + c4);
            vj = __ldg(J4 + gy * W4 + c4);
        }
        VI.x += vi.x; VI.y += vi.y; VI.z += vi.z; VI.w += vi.w;
        VJ.x += vj.x; VJ.y += vj.y; VJ.z += vj.z; VJ.w += vj.w;
        if (k >= RAD) {                        // owned row y0 + (k-7)
            const float wy = (float)(min(gy + RAD, HH - 1) - max(gy - RAD, 0) + 1);
            pII += wy * (wx0 * vi.x * vi.x + wx1 * vi.y * vi.y +
                         wx2 * vi.z * vi.z + wx3 * vi.w * vi.w);
            pJJ += wy * (wx0 * vj.x * vj.x + wx1 * vj.y * vj.y +
                         wx2 * vj.z * vj.z + wx3 * vj.w * vj.w);
            pIJ += wy * (wx0 * vi.x * vj.x + wx1 * vi.y * vj.y +
                         wx2 * vi.z * vj.z + wx3 * vi.w * vj.w);
        }
    }
    vI[(size_t)y0 * W4 + c4] = VI;
    vJ[(size_t)y0 * W4 + c4] = VJ;

    // slides: output rows y0+1 .. y0+7
    #pragma unroll
    for (int j = 0; j < 7; j++) {
        const int gyn = y0 + RAD + 1 + j;
        const int gyo = y0 - RAD + j;
        float4 ni = make_float4(0.f, 0.f, 0.f, 0.f), nj = ni, oi = ni, oj = ni;
        if (gyn < HH) {
            ni = __ldg(I4 + gyn * W4 + c4);
            nj = __ldg(J4 + gyn * W4 + c4);
        }
        if (gyo >= 0) {
            oi = __ldg(I4 + gyo * W4 + c4);
            oj = __ldg(J4 + gyo * W4 + c4);
        }
        VI.x += ni.x - oi.x; VI.y += ni.y - oi.y;
        VI.z += ni.z - oi.z; VI.w += ni.w - oi.w;
        VJ.x += nj.x - oj.x; VJ.y += nj.y - oj.y;
        VJ.z += nj.z - oj.z; VJ.w += nj.w - oj.w;
        vI[(size_t)(y0 + 1 + j) * W4 + c4] = VI;
        vJ[(size_t)(y0 + 1 + j) * W4 + c4] = VJ;
    }

    // per-CTA reduction
    double a0 = (double)pII, a1 = (double)pJJ, a2 = (double)pIJ;
    #pragma unroll
    for (int off = 16; off > 0; off >>= 1) {
        a0 += __shfl_xor_sync(0xFFFFFFFFu, a0, off);
        a1 += __shfl_xor_sync(0xFFFFFFFFu, a1, off);
        a2 += __shfl_xor_sync(0xFFFFFFFFu, a2, off);
    }
    __shared__ double red[NT / 32][3];
    if (lane == 0) { red[wrp][0] = a0; red[wrp][1] = a1; red[wrp][2] = a2; }
    __syncthreads();
    if (tid == 0) {
        double t0 = 0, t1 = 0, t2 = 0;
        #pragma unroll
        for (int w = 0; w < NT / 32; w++) { t0 += red[w][0]; t1 += red[w][1]; t2 += red[w][2]; }
        const int bid = bx + 4 * (by + 8 * bz);
        g_part[bid][0] = t0; g_part[bid][1] = t1; g_part[bid][2] = t2;
        g_part[bid][3] = 0;  g_part[bid][4] = 0;  g_part[bid][5] = 0;
    }
}

// ==================== Kernel 2: horizontal pass + finalize ===================
// grid (4, 64, 16); 256 threads. Each thread: 4 output cols (one float4) of one
// row. Loads float4 indices c4-2..c4+2 -> every warp load is 512B coalesced.
__global__ void __launch_bounds__(NT)
ncc_k2(float* __restrict__ out) {
    const int tid  = threadIdx.x;
    const int lane = tid & 31;
    const int wrp  = tid >> 5;
    const int bx = blockIdx.x, by = blockIdx.y, bz = blockIdx.z;

    const int c4 = bx * 32 + lane;     // output float4 index (0..127)
    const int y  = by * 8 + wrp;       // row (0..511)

    const float4* __restrict__ vI = g_vI + ((size_t)bz * HH + y) * W4;
    const float4* __restrict__ vJ = g_vJ + ((size_t)bz * HH + y) * W4;

    // cols c4*4-8 .. c4*4+11 (20 floats = 5 float4, zero-padded at borders)
    float rI[20], rJ[20];
    #pragma unroll
    for (int c = 0; c < 5; c++) {
        const int i4 = c4 - 2 + c;
        float4 a = make_float4(0.f, 0.f, 0.f, 0.f);
        float4 b = a;
        if (i4 >= 0 && i4 < W4) {
            a = __ldg(vI + i4);
            b = __ldg(vJ + i4);
        }
        rI[4 * c + 0] = a.x; rI[4 * c + 1] = a.y; rI[4 * c + 2] = a.z; rI[4 * c + 3] = a.w;
        rJ[4 * c + 0] = b.x; rJ[4 * c + 1] = b.y; rJ[4 * c + 2] = b.z; rJ[4 * c + 3] = b.w;
    }

    // output col i (i=0..3) window = rI[i+1 .. i+15]
    float WI = 0.f, WJ = 0.f;
    #pragma unroll
    for (int i = 1; i <= WIN; i++) { WI += rI[i]; WJ += rJ[i]; }
    float sII = 0.f, sJJ = 0.f, sIJ = 0.f;
    #pragma unroll
    for (int i = 0; i < 4; i++) {
        sII += WI * WI;
        sJJ += WJ * WJ;
        sIJ += WI * WJ;
        if (i < 3) {
            WI += rI[i + 16] - rI[i + 1];
            WJ += rJ[i + 16] - rJ[i + 1];
        }
    }

    // per-CTA reduction
    double a3 = (double)sII, a4 = (double)sJJ, a5 = (double)sIJ;
    #pragma unroll
    for (int off = 16; off > 0; off >>= 1) {
        a3 += __shfl_xor_sync(0xFFFFFFFFu, a3, off);
        a4 += __shfl_xor_sync(0xFFFFFFFFu, a4, off);
        a5 += __shfl_xor_sync(0xFFFFFFFFu, a5, off);
    }
    __shared__ double red[NT / 32][3];
    if (lane == 0) { red[wrp][0] = a3; red[wrp][1] = a4; red[wrp][2] = a5; }
    __syncthreads();

    __shared__ int s_last;
    if (tid == 0) {
        double t3 = 0, t4 = 0, t5 = 0;
        #pragma unroll
        for (int w = 0; w < NT / 32; w++) { t3 += red[w][0]; t4 += red[w][1]; t5 += red[w][2]; }
        const int bid = NB1 + bx + 4 * (by + 64 * bz);
        g_part[bid][0] = 0;  g_part[bid][1] = 0;  g_part[bid][2] = 0;
        g_part[bid][3] = t3; g_part[bid][4] = t4; g_part[bid][5] = t5;
        __threadfence();
        unsigned int prev = atomicAdd(&g_count, 1u);
        s_last = (prev == NB2 - 1);
    }
    __syncthreads();

    // -------- last CTA: global reduce over all slots + finalize --------
    if (s_last) {
        double c0 = 0, c1 = 0, c2 = 0, c3 = 0, c4d = 0, c5 = 0;
        for (int c = tid; c < NBTOT; c += NT) {
            c0 += g_part[c][0]; c1 += g_part[c][1]; c2 += g_part[c][2];
            c3 += g_part[c][3]; c4d += g_part[c][4]; c5 += g_part[c][5];
        }
        #pragma unroll
        for (int off = 16; off > 0; off >>= 1) {
            c0 += __shfl_xor_sync(0xFFFFFFFFu, c0, off);
            c1 += __shfl_xor_sync(0xFFFFFFFFu, c1, off);
            c2 += __shfl_xor_sync(0xFFFFFFFFu, c2, off);
            c3 += __shfl_xor_sync(0xFFFFFFFFu, c3, off);
            c4d += __shfl_xor_sync(0xFFFFFFFFu, c4d, off);
            c5 += __shfl_xor_sync(0xFFFFFFFFu, c5, off);
        }
        __shared__ double red2[NT / 32][6];
        if (lane == 0) {
            red2[wrp][0] = c0; red2[wrp][1] = c1; red2[wrp][2] = c2;
            red2[wrp][3] = c3; red2[wrp][4] = c4d; red2[wrp][5] = c5;
        }
        __syncthreads();
        if (tid == 0) {
            double t0 = 0, t1 = 0, t2 = 0, t3 = 0, t4 = 0, t5 = 0;
            #pragma unroll
            for (int w = 0; w < NT / 32; w++) {
                t0 += red2[w][0]; t1 += red2[w][1]; t2 += red2[w][2];
                t3 += red2[w][3]; t4 += red2[w][4]; t5 += red2[w][5];
            }
            const double inv = 1.0 / 225.0;
            const double cross = t2 - t5 * inv;
            const double iv    = t0 - t3 * inv;
            const double jv    = t1 - t4 * inv;
            out[0] = (float)(-(cross / sqrt(iv * jv)));
            g_count = 0;   // reset for next graph replay
        }
    }
}

extern "C" void kernel_launch(void* const* d_in, const int* in_sizes, int n_in,
                              void* d_out, int out_size) {
    const float* I = (const float*)d_in[0];
    const float* J = (const float*)d_in[1];
    float* out = (float*)d_out;

    dim3 g1(4, 8, 16);     // 512 CTAs
    ncc_k1<<<g1, NT>>>(I, J);
    dim3 g2(4, 64, 16);    // 4096 CTAs
    ncc_k2<<<g2, NT>>>(out);
}

// round 11
// speedup vs baseline: 2.2113x; 2.2113x over previous
#include <cuda_runtime.h>
#include <math.h>

#define BATCH 16
#define HH 512
#define WW 512
#define W4 (WW / 4)      // 128 float4 per row
#define WIN 15
#define RAD 7
#define NT 256
#define NB1 512          // k1 CTAs: (4, 8, 16)
#define NB2 1024         // k2 CTAs: (4, 16, 16), 4 row-iters per thread
#define NBTOT (NB1 + NB2)

// Intermediate vertical box-sum maps (static scratch; 16 MB each).
__device__ float4 g_vI[(size_t)BATCH * HH * W4];
__device__ float4 g_vJ[(size_t)BATCH * HH * W4];

// Partial sums: [pII,pJJ,pIJ,sII,sJJ,sIJ] per CTA slot (doubles).
__device__ double g_part[NBTOT][6];
__device__ unsigned int g_count = 0;

// Float warp reduction (no FP64 warp ops), then per-warp double handoff.
__device__ __forceinline__ void warp_red3(float& a, float& b, float& c) {
    #pragma unroll
    for (int off = 16; off > 0; off >>= 1) {
        a += __shfl_xor_sync(0xFFFFFFFFu, a, off);
        b += __shfl_xor_sync(0xFFFFFFFFu, b, off);
        c += __shfl_xor_sync(0xFFFFFFFFu, c, off);
    }
}

// ========================= Kernel 1: vertical pass ===========================
// grid (4, 8, 16); 256 threads. lane -> float4 column, warp -> 8-row group.
__global__ void __launch_bounds__(NT)
ncc_k1(const float* __restrict__ I, const float* __restrict__ J) {
    const int tid  = threadIdx.x;
    const int lane = tid & 31;
    const int wrp  = tid >> 5;
    const int bx = blockIdx.x, by = blockIdx.y, bz = blockIdx.z;

    const int c4 = bx * 32 + lane;            // float4 col index (0..127)
    const int y0 = (by * 8 + wrp) * 8;        // first owned row (0..504)
    const int cx = c4 * 4;

    const float4* __restrict__ I4 = (const float4*)I + (size_t)bz * HH * W4;
    const float4* __restrict__ J4 = (const float4*)J + (size_t)bz * HH * W4;
    float4* __restrict__ vI = g_vI + (size_t)bz * HH * W4;
    float4* __restrict__ vJ = g_vJ + (size_t)bz * HH * W4;

    const float wx0 = (float)(min(cx + 0 + RAD, WW - 1) - max(cx + 0 - RAD, 0) + 1);
    const float wx1 = (float)(min(cx + 1 + RAD, WW - 1) - max(cx + 1 - RAD, 0) + 1);
    const float wx2 = (float)(min(cx + 2 + RAD, WW - 1) - max(cx + 2 - RAD, 0) + 1);
    const float wx3 = (float)(min(cx + 3 + RAD, WW - 1) - max(cx + 3 - RAD, 0) + 1);

    float4 VI = make_float4(0.f, 0.f, 0.f, 0.f);
    float4 VJ = make_float4(0.f, 0.f, 0.f, 0.f);
    float pII = 0.f, pJJ = 0.f, pIJ = 0.f;

    // init window rows y0-7 .. y0+7 (owned rows are k=7..14)
    #pragma unroll
    for (int k = 0; k < WIN; k++) {
        const int gy = y0 - RAD + k;
        float4 vi = make_float4(0.f, 0.f, 0.f, 0.f);
        float4 vj = vi;
        if (gy >= 0 && gy < HH) {
            vi = __ldg(I4 + gy * W4 + c4);
            vj = __ldg(J4 + gy * W4 + c4);
        }
        VI.x += vi.x; VI.y += vi.y; VI.z += vi.z; VI.w += vi.w;
        VJ.x += vj.x; VJ.y += vj.y; VJ.z += vj.z; VJ.w += vj.w;
        if (k >= RAD) {
            const float wy = (float)(min(gy + RAD, HH - 1) - max(gy - RAD, 0) + 1);
            pII += wy * (wx0 * vi.x * vi.x + wx1 * vi.y * vi.y +
                         wx2 * vi.z * vi.z + wx3 * vi.w * vi.w);
            pJJ += wy * (wx0 * vj.x * vj.x + wx1 * vj.y * vj.y +
                         wx2 * vj.z * vj.z + wx3 * vj.w * vj.w);
            pIJ += wy * (wx0 * vi.x * vj.x + wx1 * vi.y * vj.y +
                         wx2 * vi.z * vj.z + wx3 * vi.w * vj.w);
        }
    }
    vI[(size_t)y0 * W4 + c4] = VI;
    vJ[(size_t)y0 * W4 + c4] = VJ;

    // slides: output rows y0+1 .. y0+7
    #pragma unroll
    for (int j = 0; j < 7; j++) {
        const int gyn = y0 + RAD + 1 + j;
        const int gyo = y0 - RAD + j;
        float4 ni = make_float4(0.f, 0.f, 0.f, 0.f), nj = ni, oi = ni, oj = ni;
        if (gyn < HH) {
            ni = __ldg(I4 + gyn * W4 + c4);
            nj = __ldg(J4 + gyn * W4 + c4);
        }
        if (gyo >= 0) {
            oi = __ldg(I4 + gyo * W4 + c4);
            oj = __ldg(J4 + gyo * W4 + c4);
        }
        VI.x += ni.x - oi.x; VI.y += ni.y - oi.y;
        VI.z += ni.z - oi.z; VI.w += ni.w - oi.w;
        VJ.x += nj.x - oj.x; VJ.y += nj.y - oj.y;
        VJ.z += nj.z - oj.z; VJ.w += nj.w - oj.w;
        vI[(size_t)(y0 + 1 + j) * W4 + c4] = VI;
        vJ[(size_t)(y0 + 1 + j) * W4 + c4] = VJ;
    }

    // ---- float warp reduction; doubles only per-warp -> tid0 ----
    warp_red3(pII, pJJ, pIJ);
    __shared__ double red[NT / 32][3];
    if (lane == 0) {
        red[wrp][0] = (double)pII; red[wrp][1] = (double)pJJ; red[wrp][2] = (double)pIJ;
    }
    __syncthreads();
    if (tid == 0) {
        double t0 = 0, t1 = 0, t2 = 0;
        #pragma unroll
        for (int w = 0; w < NT / 32; w++) { t0 += red[w][0]; t1 += red[w][1]; t2 += red[w][2]; }
        const int bid = bx + 4 * (by + 8 * bz);
        g_part[bid][0] = t0; g_part[bid][1] = t1; g_part[bid][2] = t2;
        g_part[bid][3] = 0;  g_part[bid][4] = 0;  g_part[bid][5] = 0;
    }
}

// ==================== Kernel 2: horizontal pass + finalize ===================
// grid (4, 16, 16); 256 threads; each thread: 4 rows x 4 output cols.
// Loads stay coalesced (lane -> consecutive float4 within each (iter, c) load).
__global__ void __launch_bounds__(NT)
ncc_k2(float* __restrict__ out) {
    const int tid  = threadIdx.x;
    const int lane = tid & 31;
    const int wrp  = tid >> 5;
    const int bx = blockIdx.x, by = blockIdx.y, bz = blockIdx.z;

    const int c4 = bx * 32 + lane;     // output float4 index (0..127)
    float sII = 0.f, sJJ = 0.f, sIJ = 0.f;

    #pragma unroll
    for (int k = 0; k < 4; k++) {
        const int y = by * 32 + wrp * 4 + k;    // row (0..511)
        const float4* __restrict__ vI = g_vI + ((size_t)bz * HH + y) * W4;
        const float4* __restrict__ vJ = g_vJ + ((size_t)bz * HH + y) * W4;

        float rI[20], rJ[20];
        #pragma unroll
        for (int c = 0; c < 5; c++) {
            const int i4 = c4 - 2 + c;
            float4 a = make_float4(0.f, 0.f, 0.f, 0.f);
            float4 b = a;
            if (i4 >= 0 && i4 < W4) {
                a = __ldg(vI + i4);
                b = __ldg(vJ + i4);
            }
            rI[4*c+0] = a.x; rI[4*c+1] = a.y; rI[4*c+2] = a.z; rI[4*c+3] = a.w;
            rJ[4*c+0] = b.x; rJ[4*c+1] = b.y; rJ[4*c+2] = b.z; rJ[4*c+3] = b.w;
        }

        float WI = 0.f, WJ = 0.f;
        #pragma unroll
        for (int i = 1; i <= WIN; i++) { WI += rI[i]; WJ += rJ[i]; }
        #pragma unroll
        for (int i = 0; i < 4; i++) {
            sII += WI * WI;
            sJJ += WJ * WJ;
            sIJ += WI * WJ;
            if (i < 3) {
                WI += rI[i + 16] - rI[i + 1];
                WJ += rJ[i + 16] - rJ[i + 1];
            }
        }
    }

    // ---- float warp reduction; doubles only per-warp -> tid0 ----
    warp_red3(sII, sJJ, sIJ);
    __shared__ double red[NT / 32][3];
    if (lane == 0) {
        red[wrp][0] = (double)sII; red[wrp][1] = (double)sJJ; red[wrp][2] = (double)sIJ;
    }
    __syncthreads();

    __shared__ int s_last;
    if (tid == 0) {
        double t3 = 0, t4 = 0, t5 = 0;
        #pragma unroll
        for (int w = 0; w < NT / 32; w++) { t3 += red[w][0]; t4 += red[w][1]; t5 += red[w][2]; }
        const int bid = NB1 + bx + 4 * (by + 16 * bz);
        g_part[bid][0] = 0;  g_part[bid][1] = 0;  g_part[bid][2] = 0;
        g_part[bid][3] = t3; g_part[bid][4] = t4; g_part[bid][5] = t5;
        __threadfence();
        unsigned int prev = atomicAdd(&g_count, 1u);
        s_last = (prev == NB2 - 1);
    }
    __syncthreads();

    // -------- last CTA: global reduce over all slots + finalize --------
    if (s_last) {
        double c0 = 0, c1 = 0, c2 = 0, c3 = 0, c4d = 0, c5 = 0;
        for (int c = tid; c < NBTOT; c += NT) {
            c0 += g_part[c][0]; c1 += g_part[c][1]; c2 += g_part[c][2];
            c3 += g_part[c][3]; c4d += g_part[c][4]; c5 += g_part[c][5];
        }
        // cross-warp via shared doubles (scalar DADD chains only; one CTA total)
        __shared__ double red2[NT / 32][6];
        #pragma unroll
        for (int off = 16; off > 0; off >>= 1) {
            c0 += __shfl_xor_sync(0xFFFFFFFFu, c0, off);
            c1 += __shfl_xor_sync(0xFFFFFFFFu, c1, off);
            c2 += __shfl_xor_sync(0xFFFFFFFFu, c2, off);
            c3 += __shfl_xor_sync(0xFFFFFFFFu, c3, off);
            c4d += __shfl_xor_sync(0xFFFFFFFFu, c4d, off);
            c5 += __shfl_xor_sync(0xFFFFFFFFu, c5, off);
        }
        if (lane == 0) {
            red2[wrp][0] = c0; red2[wrp][1] = c1; red2[wrp][2] = c2;
            red2[wrp][3] = c3; red2[wrp][4] = c4d; red2[wrp][5] = c5;
        }
        __syncthreads();
        if (tid == 0) {
            double t0 = 0, t1 = 0, t2 = 0, t3 = 0, t4 = 0, t5 = 0;
            #pragma unroll
            for (int w = 0; w < NT / 32; w++) {
                t0 += red2[w][0]; t1 += red2[w][1]; t2 += red2[w][2];
                t3 += red2[w][3]; t4 += red2[w][4]; t5 += red2[w][5];
            }
            const double inv = 1.0 / 225.0;
            const double cross = t2 - t5 * inv;
            const double iv    = t0 - t3 * inv;
            const double jv    = t1 - t4 * inv;
            out[0] = (float)(-(cross / sqrt(iv * jv)));
            g_count = 0;   // reset for next graph replay
        }
    }
}

extern "C" void kernel_launch(void* const* d_in, const int* in_sizes, int n_in,
                              void* d_out, int out_size) {
    const float* I = (const float*)d_in[0];
    const float* J = (const float*)d_in[1];
    float* out = (float*)d_out;

    dim3 g1(4, 8, 16);     // 512 CTAs
    ncc_k1<<<g1, NT>>>(I, J);
    dim3 g2(4, 16, 16);    // 1024 CTAs
    ncc_k2<<<g2, NT>>>(out);
}